// round 11
// baseline (speedup 1.0000x reference)
#include <cuda_runtime.h>
#include <cuda_fp16.h>
#include <math.h>

// Problem constants (fixed by setup_inputs): B=1, L=8192, H=16, D=64
#define H 16
#define L 8192
#define D 64
#define HD (H*D)      // 1024
#define BLKQ 64
#define BLKK 32
#define M 128         // L/BLKQ
#define N 256         // L/BLKK
#define T 25          // int(0.1 * N)
#define SCALE 0.125f
#define LOG2E 1.4426950408889634f
#define SC2 (SCALE*LOG2E)
#define INV_L (1.0f/8192.0f)
#define SKH 72        // smem row stride in halves (144B, 16B-multiple)
#define SVH 72

// Scratch (device globals; no allocation allowed)
__device__ float g_km[H*D];            // SUM of k over L
__device__ float g_pq[H*M*D];
__device__ float g_pkT[H*D*N];         // transposed raw pooled k: [h][d][n]
__device__ int   g_lut[H*M*T];
__device__ __half g_kh[H*L*D];         // centered k, fp16, [h][l][d]
__device__ __half g_vh[H*L*D];         // v, fp16, [h][l][d]
__device__ __half g_kfm[H*L*D];        // softmax feature map of k, fp16, [h][l][d]
__device__ float g_kvsum[H*D*D];
__device__ __half g_kvwh[H*D*D];       // (kvsum @ W^T)^T per head, fp16, [h][e][d]
__device__ float g_ksum[H*D];

// ---------------------------------------------------------------------------
// helpers
// ---------------------------------------------------------------------------
__device__ __forceinline__ float ex2(float x) {
    float r; asm("ex2.approx.f32 %0, %1;" : "=f"(r) : "f"(x)); return r;
}
__device__ __forceinline__ unsigned pk2(float lo, float hi) {
    __half2 h = __floats2half2_rn(lo, hi);
    return *(unsigned*)&h;
}
__device__ __forceinline__ void mma16(float* d, const unsigned* a, unsigned b0, unsigned b1) {
    asm volatile("mma.sync.aligned.m16n8k16.row.col.f32.f16.f16.f32 "
        "{%0,%1,%2,%3}, {%4,%5,%6,%7}, {%8,%9}, {%0,%1,%2,%3};"
        : "+f"(d[0]), "+f"(d[1]), "+f"(d[2]), "+f"(d[3])
        : "r"(a[0]), "r"(a[1]), "r"(a[2]), "r"(a[3]), "r"(b0), "r"(b1));
}
__device__ __forceinline__ void cpa16(unsigned sdst, const void* gsrc) {
    asm volatile("cp.async.cg.shared.global [%0], [%1], 16;" :: "r"(sdst), "l"(gsrc));
}
__device__ __forceinline__ void ldsm4(unsigned &r0, unsigned &r1, unsigned &r2,
                                      unsigned &r3, unsigned a) {
    asm volatile("ldmatrix.sync.aligned.m8n8.x4.shared.b16 {%0,%1,%2,%3}, [%4];"
        : "=r"(r0), "=r"(r1), "=r"(r2), "=r"(r3) : "r"(a));
}
__device__ __forceinline__ void ldsm4t(unsigned &r0, unsigned &r1, unsigned &r2,
                                       unsigned &r3, unsigned a) {
    asm volatile("ldmatrix.sync.aligned.m8n8.x4.trans.shared.b16 {%0,%1,%2,%3}, [%4];"
        : "=r"(r0), "=r"(r1), "=r"(r2), "=r"(r3) : "r"(a));
}

// ---------------------------------------------------------------------------
// K0: zero accumulators
// ---------------------------------------------------------------------------
__global__ void k_zero() {
    int t = blockIdx.x*256 + threadIdx.x;
    if (t < H*D*D) g_kvsum[t] = 0.f;
    if (t < H*D) { g_ksum[t] = 0.f; g_km[t] = 0.f; }
}

// ---------------------------------------------------------------------------
// K2: merged block pooling (q and k) + k-sum accumulation
// ---------------------------------------------------------------------------
__global__ void k_pool(const float* __restrict__ q, const float* __restrict__ k) {
    int h = blockIdx.y, d = threadIdx.x, bx = blockIdx.x;
    if (bx < M) {
        float acc = 0.f;
        #pragma unroll 4
        for (int r = 0; r < BLKQ; r++) acc += q[(bx*BLKQ + r)*HD + h*D + d];
        g_pq[(h*M + bx)*D + d] = acc / (float)BLKQ;
    } else {
        int n = bx - M;
        float acc = 0.f;
        #pragma unroll 4
        for (int r = 0; r < BLKK; r++) acc += k[(n*BLKK + r)*HD + h*D + d];
        g_pkT[(h*D + d)*N + n] = acc / (float)BLKK;
        atomicAdd(&g_km[h*D + d], acc);
    }
}

// ---------------------------------------------------------------------------
// K3: routing + top-25. grid (M, H), 512 threads; split rank loop.
// ---------------------------------------------------------------------------
__global__ __launch_bounds__(512) void k_topk() {
    int m = blockIdx.x, h = blockIdx.y, t = threadIdx.x;
    int n = t & 255, half = t >> 8;
    __shared__ float pq[64];
    __shared__ unsigned long long keys[N];
    __shared__ int r2[2][N];
    __shared__ int warpoff[8];
    if (t < 64) pq[t] = g_pq[(h*M + m)*D + t];
    __syncthreads();
    if (half == 0) {
        float s = 0.f;
        #pragma unroll 8
        for (int d = 0; d < 64; d++)
            s += pq[d] * g_pkT[(h*D + d)*N + n];
        unsigned sb = __float_as_uint(s);
        sb ^= (sb >> 31) ? 0xFFFFFFFFu : 0x80000000u;
        keys[n] = ((unsigned long long)sb << 32) | (unsigned)(N - 1 - n);
    }
    __syncthreads();
    unsigned long long mykey = keys[n];
    int rank = 0;
    int j0 = half * 128;
    #pragma unroll 8
    for (int j = j0; j < j0 + 128; j += 2) {
        ulonglong2 kk = *(ulonglong2*)&keys[j];
        rank += (kk.x > mykey) + (kk.y > mykey);
    }
    r2[half][n] = rank;
    __syncthreads();
    int w = t >> 5, lane = t & 31;
    bool sel = false;
    if (half == 0) sel = (r2[0][n] + r2[1][n]) < T;
    unsigned bal = __ballot_sync(0xffffffffu, sel);
    if (half == 0 && lane == 0) warpoff[w] = __popc(bal);
    __syncthreads();
    if (sel) {
        int pos = __popc(bal & ((1u << lane) - 1u));
        for (int i = 0; i < w; i++) pos += warpoff[i];
        g_lut[(h*M + m)*T + pos] = n;
    }
}

// ---------------------------------------------------------------------------
// K3b: convert pass — NO transposes. Row-major fp16 outputs:
//   g_kh[h][l][d] centered k; g_kfm[h][l][d] softmax(k); g_vh[h][l][d] v.
//   g_ksum via atomics. All global accesses coalesced.
// grid (256, H), 256 threads; 32 l per block, warp handles 4 rows.
// ---------------------------------------------------------------------------
__global__ __launch_bounds__(256) void k_conv(const float* __restrict__ k,
                                              const float* __restrict__ v) {
    int c = blockIdx.x, h = blockIdx.y;
    int t = threadIdx.x, w = t >> 5, lane = t & 31;
    int lc = c * 32;
    __shared__ float skm[64];
    __shared__ float sks[64];
    if (t < 64) { skm[t] = g_km[h*D + t] * INV_L; sks[t] = 0.f; }
    __syncthreads();
    float km0 = skm[2*lane], km1 = skm[2*lane + 1];
    float ka0 = 0.f, ka1 = 0.f;
    #pragma unroll
    for (int rr = 0; rr < 4; rr++) {
        int l = lc + w*4 + rr;
        float2 x = *(const float2*)&k[l*HD + h*D + 2*lane];
        float e0 = ex2(x.x * LOG2E), e1 = ex2(x.y * LOG2E);
        float sm = e0 + e1;
        #pragma unroll
        for (int off = 16; off > 0; off >>= 1)
            sm += __shfl_xor_sync(0xffffffffu, sm, off);
        float inv = 1.f / sm;
        float f0 = e0*inv, f1 = e1*inv;
        *(__half2*)&g_kfm[(h*L + l)*D + 2*lane] = __floats2half2_rn(f0, f1);
        *(__half2*)&g_kh [(h*L + l)*D + 2*lane] = __floats2half2_rn(x.x - km0, x.y - km1);
        ka0 += f0; ka1 += f1;
    }
    atomicAdd(&sks[2*lane],     ka0);
    atomicAdd(&sks[2*lane + 1], ka1);
    // v fp32 -> fp16 streaming convert
    #pragma unroll
    for (int j = 0; j < 4; j++) {
        int i = t + j*256;
        int row = i >> 5, d2 = (i & 31)*2;
        int l = lc + row;
        float2 vv = *(const float2*)&v[l*HD + h*D + d2];
        *(__half2*)&g_vh[(h*L + l)*D + d2] = __floats2half2_rn(vv.x, vv.y);
    }
    __syncthreads();
    if (t < 64) atomicAdd(&g_ksum[h*D + t], sks[t]);
}

// ---------------------------------------------------------------------------
// K5: kvsum[d][e] = sum_l kfm[l][d]*v[l][e] via tensor cores with trans
// ldmatrix (A = kfm^T, B = v, both row-major [l][.]). grid (16, H), 128 thr.
// ---------------------------------------------------------------------------
__global__ __launch_bounds__(128) void k_kvsum() {
    __shared__ __half sa[2][64*SKH];
    __shared__ __half sb[2][64*SVH];
    int c = blockIdx.x, h = blockIdx.y;
    int t = threadIdx.x, w = t >> 5, lane = t & 31;
    int g = lane >> 2, t4 = lane & 3;
    int lbase = c * 512;
    int m0 = w*16;

    auto issue = [&](int buf, int it) {
        #pragma unroll
        for (int j = 0; j < 4; j++) {
            int ch = t + j*128;
            int row = ch >> 3, c8 = (ch & 7)*8;
            cpa16((unsigned)__cvta_generic_to_shared(&sa[buf][row*SKH + c8]),
                  g_kfm + (h*L + lbase + it*64 + row)*D + c8);
            cpa16((unsigned)__cvta_generic_to_shared(&sb[buf][row*SVH + c8]),
                  g_vh  + (h*L + lbase + it*64 + row)*D + c8);
        }
        asm volatile("cp.async.commit_group;" ::: "memory");
    };

    issue(0, 0);
    issue(1, 1);

    // per-lane trans-ldmatrix offsets (bytes)
    unsigned aoff = ((((lane>>4)&1)*8 + (lane&7))*SKH)*2 + (((lane>>3)&1)*8 + m0)*2;
    unsigned boff = ((((lane>>3)&1)*8 + (lane&7))*SVH)*2 + ((lane>>4)*8)*2;

    float o[8][4];
    #pragma unroll
    for (int i = 0; i < 8; i++) { o[i][0]=0.f; o[i][1]=0.f; o[i][2]=0.f; o[i][3]=0.f; }

    for (int it = 0; it < 8; it++) {
        if (it + 1 < 8) asm volatile("cp.async.wait_group 1;" ::: "memory");
        else            asm volatile("cp.async.wait_group 0;" ::: "memory");
        __syncthreads();
        unsigned saB = (unsigned)__cvta_generic_to_shared(sa[it & 1]);
        unsigned sbB = (unsigned)__cvta_generic_to_shared(sb[it & 1]);
        #pragma unroll
        for (int ks = 0; ks < 4; ks++) {
            unsigned aa[4];
            ldsm4t(aa[0], aa[1], aa[2], aa[3], saB + aoff + ks*16*(SKH*2));
            #pragma unroll
            for (int j = 0; j < 4; j++) {
                unsigned r0, r1, r2, r3;
                ldsm4t(r0, r1, r2, r3, sbB + boff + ks*16*(SVH*2) + j*32);
                mma16(o[2*j],     aa, r0, r1);
                mma16(o[2*j + 1], aa, r2, r3);
            }
        }
        __syncthreads();
        if (it + 2 < 8) issue(it & 1, it + 2);
    }

    int d0 = w*16 + g;
    #pragma unroll
    for (int nt = 0; nt < 8; nt++) {
        int e = nt*8 + 2*t4;
        atomicAdd(&g_kvsum[h*4096 + d0*64 + e],       o[nt][0]);
        atomicAdd(&g_kvsum[h*4096 + d0*64 + e + 1],   o[nt][1]);
        atomicAdd(&g_kvsum[h*4096 + (d0+8)*64 + e],   o[nt][2]);
        atomicAdd(&g_kvsum[h*4096 + (d0+8)*64 + e+1], o[nt][3]);
    }
}

// ---------------------------------------------------------------------------
// K5b: kvwh[h][e][d] = fp16( sum_f kvsum[h][d][f] * W[e][f] )  (transposed)
// ---------------------------------------------------------------------------
__global__ void k_kvw(const float* __restrict__ W) {
    int h = blockIdx.x, t = threadIdx.x;    // 256 threads
    __shared__ float kvs[4096];
    __shared__ float WT[64*68];             // [f][e]
    __shared__ __half ob[64*SKH];           // [e][d]
    for (int i = t; i < 4096; i += 256) {
        kvs[i] = g_kvsum[h*4096 + i];
        int e = i >> 6, f = i & 63;
        WT[f*68 + e] = W[i];
    }
    __syncthreads();
    int d = t >> 2, eg = (t & 3) * 16;
    float4 a[4];
    #pragma unroll
    for (int j = 0; j < 4; j++) a[j] = make_float4(0.f, 0.f, 0.f, 0.f);
    #pragma unroll 4
    for (int f = 0; f < 64; f++) {
        float kv = kvs[d*64 + f];
        #pragma unroll
        for (int j = 0; j < 4; j++) {
            float4 wv = *(float4*)&WT[f*68 + eg + j*4];
            a[j].x += kv*wv.x; a[j].y += kv*wv.y; a[j].z += kv*wv.z; a[j].w += kv*wv.w;
        }
    }
    #pragma unroll
    for (int j = 0; j < 4; j++) {
        ob[(eg + j*4 + 0)*SKH + d] = __float2half_rn(a[j].x);
        ob[(eg + j*4 + 1)*SKH + d] = __float2half_rn(a[j].y);
        ob[(eg + j*4 + 2)*SKH + d] = __float2half_rn(a[j].z);
        ob[(eg + j*4 + 3)*SKH + d] = __float2half_rn(a[j].w);
    }
    __syncthreads();
    __half2* out2 = (__half2*)g_kvwh;
    for (int i = t; i < 2048; i += 256) {
        int e = i >> 5, d2 = (i & 31)*2;
        out2[(h*4096 + e*64 + d2) >> 1] =
            __halves2half2(ob[e*SKH + d2], ob[e*SKH + d2 + 1]);
    }
}

// ---------------------------------------------------------------------------
// K4: FUSED sparse attention + linear finalize. grid (M, H), 64 threads =
// 2 warps, each warp 32 q-rows (two m16 groups sharing every B-frag load:
// halves smem read traffic vs 4x16). V via trans-ldmatrix from row-major
// tile. Triple-buffered cp.async, one sync per stage. Epilogue overlays
// stage smem.
// ---------------------------------------------------------------------------
#define SKB (32*SKH*2)   // 4608
#define SVB (32*SVH*2)   // 4608
#define LOOPB (3*(SKB + SVB))  // 27648

__device__ __forceinline__ void issue_stage(__half* skbuf, __half* svbuf,
                                            int base, int h, int t) {
    #pragma unroll
    for (int j = 0; j < 4; j++) {
        int ch = t + j*64;               // 0..255
        int row = ch >> 3, c8 = (ch & 7)*8;
        cpa16((unsigned)__cvta_generic_to_shared(skbuf + row*SKH + c8),
              g_kh + (h*L + base + row)*D + c8);
        cpa16((unsigned)__cvta_generic_to_shared(svbuf + row*SVH + c8),
              g_vh + (h*L + base + row)*D + c8);
    }
    asm volatile("cp.async.commit_group;" ::: "memory");
}

__global__ __launch_bounds__(64, 6) void k_sparse(const float* __restrict__ q,
                                                  const float* __restrict__ bias,
                                                  float* __restrict__ out) {
    __shared__ __align__(16) char smraw[LOOPB];
    __shared__ float sksum[64], sbias[64], sinv[64];
    __shared__ int slut[32];
    __half* skbuf[3] = {(__half*)(smraw), (__half*)(smraw + SKB),
                        (__half*)(smraw + 2*SKB)};
    __half* svbuf[3] = {(__half*)(smraw + 3*SKB), (__half*)(smraw + 3*SKB + SVB),
                        (__half*)(smraw + 3*SKB + 2*SVB)};
    __half* skvw = (__half*)(smraw);            // epilogue overlay [e][d] 9216B
    __half* sqf  = (__half*)(smraw + 9216);     // epilogue overlay [l][d] 9216B

    int m = blockIdx.x, h = blockIdx.y;
    int t = threadIdx.x, w = t >> 5, lane = t & 31;
    int g = lane >> 2, t4 = lane & 3;
    int rw = w*32;

    const int* lut = &g_lut[(h*M + m)*T];
    issue_stage(skbuf[0], svbuf[0], __ldg(&lut[0])*BLKK, h, t);
    issue_stage(skbuf[1], svbuf[1], __ldg(&lut[1])*BLKK, h, t);
    if (t < T) slut[t] = lut[t];
    sksum[t] = g_ksum[h*D + t];
    sbias[t] = bias[t];

    // q A-fragments for two m16 groups (rows rw+0..15, rw+16..31)
    unsigned qa0[4][4], qa1[4][4];
    {
        const float* r0a = q + (m*64 + rw + g     )*HD + h*D;
        const float* r0b = q + (m*64 + rw + g + 8 )*HD + h*D;
        const float* r1a = q + (m*64 + rw + g + 16)*HD + h*D;
        const float* r1b = q + (m*64 + rw + g + 24)*HD + h*D;
        #pragma unroll
        for (int ks = 0; ks < 4; ks++) {
            int cc = ks*16 + 2*t4;
            float2 x;
            x = *(const float2*)&r0a[cc];     qa0[ks][0] = pk2(x.x, x.y);
            x = *(const float2*)&r0b[cc];     qa0[ks][1] = pk2(x.x, x.y);
            x = *(const float2*)&r0a[cc + 8]; qa0[ks][2] = pk2(x.x, x.y);
            x = *(const float2*)&r0b[cc + 8]; qa0[ks][3] = pk2(x.x, x.y);
            x = *(const float2*)&r1a[cc];     qa1[ks][0] = pk2(x.x, x.y);
            x = *(const float2*)&r1b[cc];     qa1[ks][1] = pk2(x.x, x.y);
            x = *(const float2*)&r1a[cc + 8]; qa1[ks][2] = pk2(x.x, x.y);
            x = *(const float2*)&r1b[cc + 8]; qa1[ks][3] = pk2(x.x, x.y);
        }
    }

    // per-lane address offsets
    unsigned lK = lane*(SKH*2);
    unsigned svoff = (((lane>>3)&1)*8 + (lane&7))*(SVH*2) + (lane>>4)*16;

    float rs0a = 0.f, rs0b = 0.f, rs1a = 0.f, rs1b = 0.f;
    float o0[8][4], o1[8][4];
    #pragma unroll
    for (int i = 0; i < 8; i++) {
        o0[i][0]=0.f; o0[i][1]=0.f; o0[i][2]=0.f; o0[i][3]=0.f;
        o1[i][0]=0.f; o1[i][1]=0.f; o1[i][2]=0.f; o1[i][3]=0.f;
    }

    for (int tt = 0; tt < T; tt++) {
        if (tt + 1 < T) asm volatile("cp.async.wait_group 1;" ::: "memory");
        else            asm volatile("cp.async.wait_group 0;" ::: "memory");
        __syncthreads();
        if (tt + 2 < T)
            issue_stage(skbuf[(tt+2)%3], svbuf[(tt+2)%3], slut[tt+2]*BLKK, h, t);

        unsigned bk  = (unsigned)__cvta_generic_to_shared(skbuf[tt%3]) + lK;
        unsigned svB = (unsigned)__cvta_generic_to_shared(svbuf[tt%3]) + svoff;

        // ---- QK: shared B-frags, mma into both row-groups ----
        float s0[4][4], s1[4][4];
        #pragma unroll
        for (int nt = 0; nt < 4; nt++) {
            s0[nt][0]=0.f; s0[nt][1]=0.f; s0[nt][2]=0.f; s0[nt][3]=0.f;
            s1[nt][0]=0.f; s1[nt][1]=0.f; s1[nt][2]=0.f; s1[nt][3]=0.f;
        }
        #pragma unroll
        for (int ks = 0; ks < 4; ks++) {
            unsigned c0[4], c1[4];
            ldsm4(c0[0], c0[1], c0[2], c0[3], bk + ks*32);
            ldsm4(c1[0], c1[1], c1[2], c1[3], bk + ks*32 + 16);
            #pragma unroll
            for (int nt = 0; nt < 4; nt++) {
                mma16(s0[nt], qa0[ks], c0[nt], c1[nt]);
                mma16(s1[nt], qa1[ks], c0[nt], c1[nt]);
            }
        }
        // ---- p = exp2(s*SC2); partial row sums ----
        float pv0[4][4], pv1[4][4];
        #pragma unroll
        for (int nt = 0; nt < 4; nt++) {
            pv0[nt][0] = ex2(s0[nt][0]*SC2); pv0[nt][1] = ex2(s0[nt][1]*SC2);
            pv0[nt][2] = ex2(s0[nt][2]*SC2); pv0[nt][3] = ex2(s0[nt][3]*SC2);
            pv1[nt][0] = ex2(s1[nt][0]*SC2); pv1[nt][1] = ex2(s1[nt][1]*SC2);
            pv1[nt][2] = ex2(s1[nt][2]*SC2); pv1[nt][3] = ex2(s1[nt][3]*SC2);
            rs0a += pv0[nt][0] + pv0[nt][1];
            rs0b += pv0[nt][2] + pv0[nt][3];
            rs1a += pv1[nt][0] + pv1[nt][1];
            rs1b += pv1[nt][2] + pv1[nt][3];
        }
        // ---- PV: trans-ldmatrix V B-frags shared by both groups ----
        #pragma unroll
        for (int ks2 = 0; ks2 < 2; ks2++) {
            unsigned pa0[4], pa1[4];
            pa0[0] = pk2(pv0[2*ks2  ][0], pv0[2*ks2  ][1]);
            pa0[1] = pk2(pv0[2*ks2  ][2], pv0[2*ks2  ][3]);
            pa0[2] = pk2(pv0[2*ks2+1][0], pv0[2*ks2+1][1]);
            pa0[3] = pk2(pv0[2*ks2+1][2], pv0[2*ks2+1][3]);
            pa1[0] = pk2(pv1[2*ks2  ][0], pv1[2*ks2  ][1]);
            pa1[1] = pk2(pv1[2*ks2  ][2], pv1[2*ks2  ][3]);
            pa1[2] = pk2(pv1[2*ks2+1][0], pv1[2*ks2+1][1]);
            pa1[3] = pk2(pv1[2*ks2+1][2], pv1[2*ks2+1][3]);
            unsigned sb2 = svB + ks2*16*(SVH*2);
            #pragma unroll
            for (int j = 0; j < 4; j++) {
                unsigned r0, r1, r2, r3;
                ldsm4t(r0, r1, r2, r3, sb2 + j*32);
                mma16(o0[2*j],   pa0, r0, r1);
                mma16(o0[2*j+1], pa0, r2, r3);
                mma16(o1[2*j],   pa1, r0, r1);
                mma16(o1[2*j+1], pa1, r2, r3);
            }
        }
    }

    // row sums (quad reduce) + inverses
    #pragma unroll
    for (int off = 1; off <= 2; off <<= 1) {
        rs0a += __shfl_xor_sync(0xffffffffu, rs0a, off);
        rs0b += __shfl_xor_sync(0xffffffffu, rs0b, off);
        rs1a += __shfl_xor_sync(0xffffffffu, rs1a, off);
        rs1b += __shfl_xor_sync(0xffffffffu, rs1b, off);
    }
    float i0a = 1.f/rs0a, i0b = 1.f/rs0b, i1a = 1.f/rs1a, i1b = 1.f/rs1b;

    __syncthreads();   // stage buffers dead; overlay safe

    // load kvwh into overlay smem (16 uint2 per thread)
    for (int i = t; i < 1024; i += 64) {
        int e = i >> 4, c4 = (i & 15)*4;
        *(uint2*)&skvw[e*SKH + c4] = *(const uint2*)&g_kvwh[(h*64 + e)*64 + c4];
    }
    // q feature map (no-max softmax), warp w rows rw..rw+31
    for (int rr = 0; rr < 32; rr++) {
        int row = rw + rr;
        int l = m*64 + row;
        float2 x = *(const float2*)&q[l*HD + h*D + 2*lane];
        float e0 = ex2(x.x * LOG2E), e1 = ex2(x.y * LOG2E);
        float sm = e0 + e1;
        #pragma unroll
        for (int off = 16; off > 0; off >>= 1)
            sm += __shfl_xor_sync(0xffffffffu, sm, off);
        float inv = 1.f / sm;
        float q0 = e0*inv, q1 = e1*inv;
        *(__half2*)&sqf[row*SKH + 2*lane] = __floats2half2_rn(q0, q1);
        float dp = q0*sksum[2*lane] + q1*sksum[2*lane + 1];
        #pragma unroll
        for (int off = 16; off > 0; off >>= 1)
            dp += __shfl_xor_sync(0xffffffffu, dp, off);
        if (lane == 0) sinv[row] = 1.f / (dp + 1e-6f);
    }
    __syncthreads();

    // linear mma for both groups
    float l0[8][4], l1[8][4];
    #pragma unroll
    for (int i = 0; i < 8; i++) {
        l0[i][0]=0.f; l0[i][1]=0.f; l0[i][2]=0.f; l0[i][3]=0.f;
        l1[i][0]=0.f; l1[i][1]=0.f; l1[i][2]=0.f; l1[i][3]=0.f;
    }
    #pragma unroll
    for (int ks = 0; ks < 4; ks++) {
        unsigned a0[4], a1[4];
        int cc = ks*16 + 2*t4;
        a0[0] = *(const unsigned*)&sqf[(rw + g     )*SKH + cc];
        a0[1] = *(const unsigned*)&sqf[(rw + g + 8 )*SKH + cc];
        a0[2] = *(const unsigned*)&sqf[(rw + g     )*SKH + cc + 8];
        a0[3] = *(const unsigned*)&sqf[(rw + g + 8 )*SKH + cc + 8];
        a1[0] = *(const unsigned*)&sqf[(rw + g + 16)*SKH + cc];
        a1[1] = *(const unsigned*)&sqf[(rw + g + 24)*SKH + cc];
        a1[2] = *(const unsigned*)&sqf[(rw + g + 16)*SKH + cc + 8];
        a1[3] = *(const unsigned*)&sqf[(rw + g + 24)*SKH + cc + 8];
        #pragma unroll
        for (int nt = 0; nt < 8; nt++) {
            unsigned b0 = *(const unsigned*)&skvw[(nt*8 + g)*SKH + cc];
            unsigned b1 = *(const unsigned*)&skvw[(nt*8 + g)*SKH + cc + 8];
            mma16(l0[nt], a0, b0, b1);
            mma16(l1[nt], a1, b0, b1);
        }
    }

    // combine + write out [l][h][d]
    int lg = m*64 + rw + g;
    float v0a = sinv[rw + g],      v0b = sinv[rw + g + 8];
    float v1a = sinv[rw + g + 16], v1b = sinv[rw + g + 24];
    #pragma unroll
    for (int nt = 0; nt < 8; nt++) {
        int col = nt*8 + 2*t4;
        float b0 = sbias[col], b1 = sbias[col + 1];
        *(float2*)&out[(lg     )*HD + h*D + col] =
            make_float2(o0[nt][0]*i0a + l0[nt][0]*v0a + b0,
                        o0[nt][1]*i0a + l0[nt][1]*v0a + b1);
        *(float2*)&out[(lg + 8 )*HD + h*D + col] =
            make_float2(o0[nt][2]*i0b + l0[nt][2]*v0b + b0,
                        o0[nt][3]*i0b + l0[nt][3]*v0b + b1);
        *(float2*)&out[(lg + 16)*HD + h*D + col] =
            make_float2(o1[nt][0]*i1a + l1[nt][0]*v1a + b0,
                        o1[nt][1]*i1a + l1[nt][1]*v1a + b1);
        *(float2*)&out[(lg + 24)*HD + h*D + col] =
            make_float2(o1[nt][2]*i1b + l1[nt][2]*v1b + b0,
                        o1[nt][3]*i1b + l1[nt][3]*v1b + b1);
    }
}

// ---------------------------------------------------------------------------
extern "C" void kernel_launch(void* const* d_in, const int* in_sizes, int n_in,
                              void* d_out, int out_size) {
    const float* q = (const float*)d_in[0];
    const float* k = (const float*)d_in[1];
    const float* v = (const float*)d_in[2];
    const float* W = (const float*)d_in[3];
    const float* b = (const float*)d_in[4];
    float* out = (float*)d_out;

    k_zero  <<<(H*D*D + 255)/256, 256>>>();
    k_pool  <<<dim3(M + N, H), 64>>>(q, k);
    k_topk  <<<dim3(M, H), 512>>>();
    k_conv  <<<dim3(256, H), 256>>>(k, v);
    k_kvsum <<<dim3(16, H), 128>>>();
    k_kvw   <<<H, 256>>>(W);
    k_sparse<<<dim3(M, H), 64>>>(q, b, out);
}

// round 13
// speedup vs baseline: 1.5638x; 1.5638x over previous
#include <cuda_runtime.h>
#include <cuda_fp16.h>
#include <math.h>

// Problem constants (fixed by setup_inputs): B=1, L=8192, H=16, D=64
#define H 16
#define L 8192
#define D 64
#define HD (H*D)      // 1024
#define BLKQ 64
#define BLKK 32
#define M 128         // L/BLKQ
#define N 256         // L/BLKK
#define T 25          // int(0.1 * N)
#define SCALE 0.125f
#define LOG2E 1.4426950408889634f
#define SC2 (SCALE*LOG2E)
#define INV_L (1.0f/8192.0f)
#define SKH 72        // smem row stride in halves (144B, 16B-multiple)
#define SVH 72

// Scratch (device globals; no allocation allowed)
__device__ float g_km[H*D];            // SUM of k over L
__device__ float g_pq[H*M*D];
__device__ float g_pkT[H*D*N];         // transposed raw pooled k: [h][d][n]
__device__ int   g_lut[H*M*T];
__device__ __half g_kh[H*L*D];         // centered k, fp16, [h][l][d]
__device__ __half g_vh[H*L*D];         // v, fp16, [h][l][d]
__device__ __half g_kfm[H*L*D];        // softmax feature map of k, fp16, [h][l][d]
__device__ float g_kvsum[H*D*D];
__device__ __half g_kvwh[H*D*D];       // (kvsum @ W^T)^T per head, fp16, [h][e][d]
__device__ float g_ksum[H*D];

// ---------------------------------------------------------------------------
// helpers
// ---------------------------------------------------------------------------
__device__ __forceinline__ float ex2(float x) {
    float r; asm("ex2.approx.f32 %0, %1;" : "=f"(r) : "f"(x)); return r;
}
__device__ __forceinline__ unsigned pk2(float lo, float hi) {
    __half2 h = __floats2half2_rn(lo, hi);
    return *(unsigned*)&h;
}
__device__ __forceinline__ void mma16(float* d, const unsigned* a, unsigned b0, unsigned b1) {
    asm volatile("mma.sync.aligned.m16n8k16.row.col.f32.f16.f16.f32 "
        "{%0,%1,%2,%3}, {%4,%5,%6,%7}, {%8,%9}, {%0,%1,%2,%3};"
        : "+f"(d[0]), "+f"(d[1]), "+f"(d[2]), "+f"(d[3])
        : "r"(a[0]), "r"(a[1]), "r"(a[2]), "r"(a[3]), "r"(b0), "r"(b1));
}
__device__ __forceinline__ void cpa16(unsigned sdst, const void* gsrc) {
    asm volatile("cp.async.cg.shared.global [%0], [%1], 16;" :: "r"(sdst), "l"(gsrc));
}
__device__ __forceinline__ void ldsm4(unsigned &r0, unsigned &r1, unsigned &r2,
                                      unsigned &r3, unsigned a) {
    asm volatile("ldmatrix.sync.aligned.m8n8.x4.shared.b16 {%0,%1,%2,%3}, [%4];"
        : "=r"(r0), "=r"(r1), "=r"(r2), "=r"(r3) : "r"(a));
}
__device__ __forceinline__ void ldsm4t(unsigned &r0, unsigned &r1, unsigned &r2,
                                       unsigned &r3, unsigned a) {
    asm volatile("ldmatrix.sync.aligned.m8n8.x4.trans.shared.b16 {%0,%1,%2,%3}, [%4];"
        : "=r"(r0), "=r"(r1), "=r"(r2), "=r"(r3) : "r"(a));
}

// ---------------------------------------------------------------------------
// K0: zero accumulators
// ---------------------------------------------------------------------------
__global__ void k_zero() {
    int t = blockIdx.x*256 + threadIdx.x;
    if (t < H*D*D) g_kvsum[t] = 0.f;
    if (t < H*D) { g_ksum[t] = 0.f; g_km[t] = 0.f; }
}

// ---------------------------------------------------------------------------
// K2: merged block pooling (q and k) + k-sum accumulation
// ---------------------------------------------------------------------------
__global__ void k_pool(const float* __restrict__ q, const float* __restrict__ k) {
    int h = blockIdx.y, d = threadIdx.x, bx = blockIdx.x;
    if (bx < M) {
        float acc = 0.f;
        #pragma unroll 4
        for (int r = 0; r < BLKQ; r++) acc += q[(bx*BLKQ + r)*HD + h*D + d];
        g_pq[(h*M + bx)*D + d] = acc / (float)BLKQ;
    } else {
        int n = bx - M;
        float acc = 0.f;
        #pragma unroll 4
        for (int r = 0; r < BLKK; r++) acc += k[(n*BLKK + r)*HD + h*D + d];
        g_pkT[(h*D + d)*N + n] = acc / (float)BLKK;
        atomicAdd(&g_km[h*D + d], acc);
    }
}

// ---------------------------------------------------------------------------
// K3: routing + top-25. grid (M, H), 512 threads; split rank loop.
// ---------------------------------------------------------------------------
__global__ __launch_bounds__(512) void k_topk() {
    int m = blockIdx.x, h = blockIdx.y, t = threadIdx.x;
    int n = t & 255, half = t >> 8;
    __shared__ float pq[64];
    __shared__ unsigned long long keys[N];
    __shared__ int r2[2][N];
    __shared__ int warpoff[8];
    if (t < 64) pq[t] = g_pq[(h*M + m)*D + t];
    __syncthreads();
    if (half == 0) {
        float s = 0.f;
        #pragma unroll 8
        for (int d = 0; d < 64; d++)
            s += pq[d] * g_pkT[(h*D + d)*N + n];
        unsigned sb = __float_as_uint(s);
        sb ^= (sb >> 31) ? 0xFFFFFFFFu : 0x80000000u;
        keys[n] = ((unsigned long long)sb << 32) | (unsigned)(N - 1 - n);
    }
    __syncthreads();
    unsigned long long mykey = keys[n];
    int rank = 0;
    int j0 = half * 128;
    #pragma unroll 8
    for (int j = j0; j < j0 + 128; j += 2) {
        ulonglong2 kk = *(ulonglong2*)&keys[j];
        rank += (kk.x > mykey) + (kk.y > mykey);
    }
    r2[half][n] = rank;
    __syncthreads();
    int w = t >> 5, lane = t & 31;
    bool sel = false;
    if (half == 0) sel = (r2[0][n] + r2[1][n]) < T;
    unsigned bal = __ballot_sync(0xffffffffu, sel);
    if (half == 0 && lane == 0) warpoff[w] = __popc(bal);
    __syncthreads();
    if (sel) {
        int pos = __popc(bal & ((1u << lane) - 1u));
        for (int i = 0; i < w; i++) pos += warpoff[i];
        g_lut[(h*M + m)*T + pos] = n;
    }
}

// ---------------------------------------------------------------------------
// K3b: convert pass — row-major fp16 outputs, no transposes, all coalesced.
// grid (256, H), 256 threads; 32 l per block, warp handles 4 rows.
// ---------------------------------------------------------------------------
__global__ __launch_bounds__(256) void k_conv(const float* __restrict__ k,
                                              const float* __restrict__ v) {
    int c = blockIdx.x, h = blockIdx.y;
    int t = threadIdx.x, w = t >> 5, lane = t & 31;
    int lc = c * 32;
    __shared__ float skm[64];
    __shared__ float sks[64];
    if (t < 64) { skm[t] = g_km[h*D + t] * INV_L; sks[t] = 0.f; }
    __syncthreads();
    float km0 = skm[2*lane], km1 = skm[2*lane + 1];
    float ka0 = 0.f, ka1 = 0.f;
    #pragma unroll
    for (int rr = 0; rr < 4; rr++) {
        int l = lc + w*4 + rr;
        float2 x = *(const float2*)&k[l*HD + h*D + 2*lane];
        float e0 = ex2(x.x * LOG2E), e1 = ex2(x.y * LOG2E);
        float sm = e0 + e1;
        #pragma unroll
        for (int off = 16; off > 0; off >>= 1)
            sm += __shfl_xor_sync(0xffffffffu, sm, off);
        float inv = 1.f / sm;
        float f0 = e0*inv, f1 = e1*inv;
        *(__half2*)&g_kfm[(h*L + l)*D + 2*lane] = __floats2half2_rn(f0, f1);
        *(__half2*)&g_kh [(h*L + l)*D + 2*lane] = __floats2half2_rn(x.x - km0, x.y - km1);
        ka0 += f0; ka1 += f1;
    }
    atomicAdd(&sks[2*lane],     ka0);
    atomicAdd(&sks[2*lane + 1], ka1);
    #pragma unroll
    for (int j = 0; j < 4; j++) {
        int i = t + j*256;
        int row = i >> 5, d2 = (i & 31)*2;
        int l = lc + row;
        float2 vv = *(const float2*)&v[l*HD + h*D + d2];
        *(__half2*)&g_vh[(h*L + l)*D + d2] = __floats2half2_rn(vv.x, vv.y);
    }
    __syncthreads();
    if (t < 64) atomicAdd(&g_ksum[h*D + t], sks[t]);
}

// ---------------------------------------------------------------------------
// K5: kvsum[d][e] = sum_l kfm[l][d]*v[l][e] via tensor cores with trans
// ldmatrix (A = kfm^T, B = v, both row-major [l][.]). grid (16, H), 128 thr.
// ---------------------------------------------------------------------------
__global__ __launch_bounds__(128) void k_kvsum() {
    __shared__ __half sa[2][64*SKH];
    __shared__ __half sb[2][64*SVH];
    int c = blockIdx.x, h = blockIdx.y;
    int t = threadIdx.x, w = t >> 5, lane = t & 31;
    int g = lane >> 2, t4 = lane & 3;
    int lbase = c * 512;
    int m0 = w*16;

    auto issue = [&](int buf, int it) {
        #pragma unroll
        for (int j = 0; j < 4; j++) {
            int ch = t + j*128;
            int row = ch >> 3, c8 = (ch & 7)*8;
            cpa16((unsigned)__cvta_generic_to_shared(&sa[buf][row*SKH + c8]),
                  g_kfm + (h*L + lbase + it*64 + row)*D + c8);
            cpa16((unsigned)__cvta_generic_to_shared(&sb[buf][row*SVH + c8]),
                  g_vh  + (h*L + lbase + it*64 + row)*D + c8);
        }
        asm volatile("cp.async.commit_group;" ::: "memory");
    };

    issue(0, 0);
    issue(1, 1);

    unsigned aoff = ((((lane>>4)&1)*8 + (lane&7))*SKH)*2 + (((lane>>3)&1)*8 + m0)*2;
    unsigned boff = ((((lane>>3)&1)*8 + (lane&7))*SVH)*2 + ((lane>>4)*8)*2;

    float o[8][4];
    #pragma unroll
    for (int i = 0; i < 8; i++) { o[i][0]=0.f; o[i][1]=0.f; o[i][2]=0.f; o[i][3]=0.f; }

    for (int it = 0; it < 8; it++) {
        if (it + 1 < 8) asm volatile("cp.async.wait_group 1;" ::: "memory");
        else            asm volatile("cp.async.wait_group 0;" ::: "memory");
        __syncthreads();
        unsigned saB = (unsigned)__cvta_generic_to_shared(sa[it & 1]);
        unsigned sbB = (unsigned)__cvta_generic_to_shared(sb[it & 1]);
        #pragma unroll
        for (int ks = 0; ks < 4; ks++) {
            unsigned aa[4];
            ldsm4t(aa[0], aa[1], aa[2], aa[3], saB + aoff + ks*16*(SKH*2));
            #pragma unroll
            for (int j = 0; j < 4; j++) {
                unsigned r0, r1, r2, r3;
                ldsm4t(r0, r1, r2, r3, sbB + boff + ks*16*(SVH*2) + j*32);
                mma16(o[2*j],     aa, r0, r1);
                mma16(o[2*j + 1], aa, r2, r3);
            }
        }
        __syncthreads();
        if (it + 2 < 8) issue(it & 1, it + 2);
    }

    int d0 = w*16 + g;
    #pragma unroll
    for (int nt = 0; nt < 8; nt++) {
        int e = nt*8 + 2*t4;
        atomicAdd(&g_kvsum[h*4096 + d0*64 + e],       o[nt][0]);
        atomicAdd(&g_kvsum[h*4096 + d0*64 + e + 1],   o[nt][1]);
        atomicAdd(&g_kvsum[h*4096 + (d0+8)*64 + e],   o[nt][2]);
        atomicAdd(&g_kvsum[h*4096 + (d0+8)*64 + e+1], o[nt][3]);
    }
}

// ---------------------------------------------------------------------------
// K5b: kvwh[h][e][d] = fp16( sum_f kvsum[h][d][f] * W[e][f] )  (transposed)
// ---------------------------------------------------------------------------
__global__ void k_kvw(const float* __restrict__ W) {
    int h = blockIdx.x, t = threadIdx.x;    // 256 threads
    __shared__ float kvs[4096];
    __shared__ float WT[64*68];             // [f][e]
    __shared__ __half ob[64*SKH];           // [e][d]
    for (int i = t; i < 4096; i += 256) {
        kvs[i] = g_kvsum[h*4096 + i];
        int e = i >> 6, f = i & 63;
        WT[f*68 + e] = W[i];
    }
    __syncthreads();
    int d = t >> 2, eg = (t & 3) * 16;
    float4 a[4];
    #pragma unroll
    for (int j = 0; j < 4; j++) a[j] = make_float4(0.f, 0.f, 0.f, 0.f);
    #pragma unroll 4
    for (int f = 0; f < 64; f++) {
        float kv = kvs[d*64 + f];
        #pragma unroll
        for (int j = 0; j < 4; j++) {
            float4 wv = *(float4*)&WT[f*68 + eg + j*4];
            a[j].x += kv*wv.x; a[j].y += kv*wv.y; a[j].z += kv*wv.z; a[j].w += kv*wv.w;
        }
    }
    #pragma unroll
    for (int j = 0; j < 4; j++) {
        ob[(eg + j*4 + 0)*SKH + d] = __float2half_rn(a[j].x);
        ob[(eg + j*4 + 1)*SKH + d] = __float2half_rn(a[j].y);
        ob[(eg + j*4 + 2)*SKH + d] = __float2half_rn(a[j].z);
        ob[(eg + j*4 + 3)*SKH + d] = __float2half_rn(a[j].w);
    }
    __syncthreads();
    __half2* out2 = (__half2*)g_kvwh;
    for (int i = t; i < 2048; i += 256) {
        int e = i >> 5, d2 = (i & 31)*2;
        out2[(h*4096 + e*64 + d2) >> 1] =
            __halves2half2(ob[e*SKH + d2], ob[e*SKH + d2 + 1]);
    }
}

// ---------------------------------------------------------------------------
// K4: FUSED sparse attention + linear finalize. grid (M, H), 128 threads =
// 4 warps x 16 rows (the proven R10 shape). V row-major [l][d] staged 32x64,
// B-frags via trans-ldmatrix. Triple-buffered cp.async, one sync per stage.
// Epilogue (q feature map + linear mma) overlays stage smem.
// ---------------------------------------------------------------------------
#define SKB (32*SKH*2)   // 4608
#define SVB (32*SVH*2)   // 4608
#define LOOPB (3*(SKB + SVB))  // 27648

__device__ __forceinline__ void issue_stage(__half* skbuf, __half* svbuf,
                                            int base, int h, int t) {
    #pragma unroll
    for (int j = 0; j < 2; j++) {
        int ch = t + j*128;              // 0..255
        int row = ch >> 3, c8 = (ch & 7)*8;
        cpa16((unsigned)__cvta_generic_to_shared(skbuf + row*SKH + c8),
              g_kh + (h*L + base + row)*D + c8);
        cpa16((unsigned)__cvta_generic_to_shared(svbuf + row*SVH + c8),
              g_vh + (h*L + base + row)*D + c8);
    }
    asm volatile("cp.async.commit_group;" ::: "memory");
}

__global__ __launch_bounds__(128, 4) void k_sparse(const float* __restrict__ q,
                                                   const float* __restrict__ bias,
                                                   float* __restrict__ out) {
    __shared__ __align__(16) char smraw[LOOPB];
    __shared__ float sksum[64], sbias[64], sinv[64];
    __shared__ int slut[32];
    __half* skbuf[3] = {(__half*)(smraw), (__half*)(smraw + SKB),
                        (__half*)(smraw + 2*SKB)};
    __half* svbuf[3] = {(__half*)(smraw + 3*SKB), (__half*)(smraw + 3*SKB + SVB),
                        (__half*)(smraw + 3*SKB + 2*SVB)};
    __half* skvw = (__half*)(smraw);            // epilogue overlay [e][d] 9216B
    __half* sqf  = (__half*)(smraw + 9216);     // epilogue overlay [l][d] 9216B

    int m = blockIdx.x, h = blockIdx.y;
    int t = threadIdx.x, w = t >> 5, lane = t & 31;
    int g = lane >> 2, t4 = lane & 3;

    const int* lut = &g_lut[(h*M + m)*T];
    issue_stage(skbuf[0], svbuf[0], __ldg(&lut[0])*BLKK, h, t);
    issue_stage(skbuf[1], svbuf[1], __ldg(&lut[1])*BLKK, h, t);
    if (t < T) slut[t] = lut[t];
    if (t < 64) { sksum[t] = g_ksum[h*D + t]; sbias[t] = bias[t]; }

    // q A-fragments directly from global (fp16)
    const float* qr0 = q + (m*64 + w*16 + g)*HD + h*D;
    const float* qr1 = qr0 + 8*HD;
    unsigned qa[4][4];
    #pragma unroll
    for (int ks = 0; ks < 4; ks++) {
        float2 a0 = *(const float2*)&qr0[ks*16 + 2*t4];
        float2 b0 = *(const float2*)&qr1[ks*16 + 2*t4];
        float2 a1 = *(const float2*)&qr0[ks*16 + 2*t4 + 8];
        float2 b1 = *(const float2*)&qr1[ks*16 + 2*t4 + 8];
        qa[ks][0] = pk2(a0.x, a0.y);
        qa[ks][1] = pk2(b0.x, b0.y);
        qa[ks][2] = pk2(a1.x, a1.y);
        qa[ks][3] = pk2(b1.x, b1.y);
    }

    unsigned lK = lane*(SKH*2);
    unsigned svoff = (((lane>>3)&1)*8 + (lane&7))*(SVH*2) + (lane>>4)*16;

    float rsum0 = 0.f, rsum1 = 0.f;
    float o[8][4];
    #pragma unroll
    for (int i = 0; i < 8; i++) { o[i][0]=0.f; o[i][1]=0.f; o[i][2]=0.f; o[i][3]=0.f; }

    for (int tt = 0; tt < T; tt++) {
        if (tt + 1 < T) asm volatile("cp.async.wait_group 1;" ::: "memory");
        else            asm volatile("cp.async.wait_group 0;" ::: "memory");
        __syncthreads();
        if (tt + 2 < T)
            issue_stage(skbuf[(tt+2)%3], svbuf[(tt+2)%3], slut[tt+2]*BLKK, h, t);

        unsigned bk  = (unsigned)__cvta_generic_to_shared(skbuf[tt%3]) + lK;
        unsigned svB = (unsigned)__cvta_generic_to_shared(svbuf[tt%3]) + svoff;

        // ---- QK: ldmatrix.x4 B-frags, 4 k-steps x 4 n-tiles ----
        float s[4][4];
        #pragma unroll
        for (int nt = 0; nt < 4; nt++) { s[nt][0]=0.f; s[nt][1]=0.f; s[nt][2]=0.f; s[nt][3]=0.f; }
        #pragma unroll
        for (int ks = 0; ks < 4; ks++) {
            unsigned c0[4], c1[4];
            ldsm4(c0[0], c0[1], c0[2], c0[3], bk + ks*32);
            ldsm4(c1[0], c1[1], c1[2], c1[3], bk + ks*32 + 16);
            #pragma unroll
            for (int nt = 0; nt < 4; nt++)
                mma16(s[nt], qa[ks], c0[nt], c1[nt]);
        }
        // ---- p = exp2(s * SC2), per-lane partial row sums ----
        float pv[4][4];
        #pragma unroll
        for (int nt = 0; nt < 4; nt++) {
            pv[nt][0] = ex2(s[nt][0]*SC2);
            pv[nt][1] = ex2(s[nt][1]*SC2);
            pv[nt][2] = ex2(s[nt][2]*SC2);
            pv[nt][3] = ex2(s[nt][3]*SC2);
            rsum0 += pv[nt][0] + pv[nt][1];
            rsum1 += pv[nt][2] + pv[nt][3];
        }
        // ---- PV: trans-ldmatrix V B-frags from row-major tile ----
        #pragma unroll
        for (int ks2 = 0; ks2 < 2; ks2++) {
            unsigned pa[4];
            pa[0] = pk2(pv[2*ks2  ][0], pv[2*ks2  ][1]);
            pa[1] = pk2(pv[2*ks2  ][2], pv[2*ks2  ][3]);
            pa[2] = pk2(pv[2*ks2+1][0], pv[2*ks2+1][1]);
            pa[3] = pk2(pv[2*ks2+1][2], pv[2*ks2+1][3]);
            unsigned sb2 = svB + ks2*16*(SVH*2);
            #pragma unroll
            for (int j = 0; j < 4; j++) {
                unsigned r0, r1, r2, r3;
                ldsm4t(r0, r1, r2, r3, sb2 + j*32);
                mma16(o[2*j],   pa, r0, r1);
                mma16(o[2*j+1], pa, r2, r3);
            }
        }
    }

    // sparse row sums (quad reduce)
    #pragma unroll
    for (int off = 1; off <= 2; off <<= 1) {
        rsum0 += __shfl_xor_sync(0xffffffffu, rsum0, off);
        rsum1 += __shfl_xor_sync(0xffffffffu, rsum1, off);
    }
    float inv0 = 1.f / rsum0, inv1 = 1.f / rsum1;

    __syncthreads();   // stage buffers dead; overlay safe

    // load kvwh into overlay smem
    for (int i = t; i < 1024; i += 128) {
        int e = i >> 4, c4 = (i & 15)*4;
        *(uint2*)&skvw[e*SKH + c4] = *(const uint2*)&g_kvwh[(h*64 + e)*64 + c4];
    }
    // q feature map (no-max softmax) for own warp's 16 rows
    for (int rr = 0; rr < 16; rr++) {
        int row = w*16 + rr;
        int l = m*64 + row;
        float2 x = *(const float2*)&q[l*HD + h*D + 2*lane];
        float e0 = ex2(x.x * LOG2E), e1 = ex2(x.y * LOG2E);
        float sm = e0 + e1;
        #pragma unroll
        for (int off = 16; off > 0; off >>= 1)
            sm += __shfl_xor_sync(0xffffffffu, sm, off);
        float inv = 1.f / sm;
        float q0 = e0*inv, q1 = e1*inv;
        *(__half2*)&sqf[row*SKH + 2*lane] = __floats2half2_rn(q0, q1);
        float dp = q0*sksum[2*lane] + q1*sksum[2*lane + 1];
        #pragma unroll
        for (int off = 16; off > 0; off >>= 1)
            dp += __shfl_xor_sync(0xffffffffu, dp, off);
        if (lane == 0) sinv[row] = 1.f / (dp + 1e-6f);
    }
    __syncthreads();   // skvw + sqf visible to all warps

    float ol[8][4];
    #pragma unroll
    for (int i = 0; i < 8; i++) { ol[i][0]=0.f; ol[i][1]=0.f; ol[i][2]=0.f; ol[i][3]=0.f; }
    #pragma unroll
    for (int ks = 0; ks < 4; ks++) {
        unsigned aa[4];
        int cc = ks*16 + 2*t4;
        aa[0] = *(const unsigned*)&sqf[(w*16 + g    )*SKH + cc];
        aa[1] = *(const unsigned*)&sqf[(w*16 + g + 8)*SKH + cc];
        aa[2] = *(const unsigned*)&sqf[(w*16 + g    )*SKH + cc + 8];
        aa[3] = *(const unsigned*)&sqf[(w*16 + g + 8)*SKH + cc + 8];
        #pragma unroll
        for (int nt = 0; nt < 8; nt++) {
            unsigned b0 = *(const unsigned*)&skvw[(nt*8 + g)*SKH + cc];
            unsigned b1 = *(const unsigned*)&skvw[(nt*8 + g)*SKH + cc + 8];
            mma16(ol[nt], aa, b0, b1);
        }
    }

    // ---- combine + write out [l][h][d] ----
    int rg = w*16 + g;
    int l0 = m*64 + rg;
    float iv0 = sinv[rg], iv1 = sinv[rg + 8];
    #pragma unroll
    for (int nt = 0; nt < 8; nt++) {
        int col = nt*8 + 2*t4;
        *(float2*)&out[(l0    )*HD + h*D + col] =
            make_float2(o[nt][0]*inv0 + ol[nt][0]*iv0 + sbias[col],
                        o[nt][1]*inv0 + ol[nt][1]*iv0 + sbias[col+1]);
        *(float2*)&out[(l0 + 8)*HD + h*D + col] =
            make_float2(o[nt][2]*inv1 + ol[nt][2]*iv1 + sbias[col],
                        o[nt][3]*inv1 + ol[nt][3]*iv1 + sbias[col+1]);
    }
}

// ---------------------------------------------------------------------------
extern "C" void kernel_launch(void* const* d_in, const int* in_sizes, int n_in,
                              void* d_out, int out_size) {
    const float* q = (const float*)d_in[0];
    const float* k = (const float*)d_in[1];
    const float* v = (const float*)d_in[2];
    const float* W = (const float*)d_in[3];
    const float* b = (const float*)d_in[4];
    float* out = (float*)d_out;

    k_zero  <<<(H*D*D + 255)/256, 256>>>();
    k_pool  <<<dim3(M + N, H), 64>>>(q, k);
    k_topk  <<<dim3(M, H), 512>>>();
    k_conv  <<<dim3(256, H), 256>>>(k, v);
    k_kvsum <<<dim3(16, H), 128>>>();
    k_kvw   <<<H, 256>>>(W);
    k_sparse<<<dim3(M, H), 128>>>(q, b, out);
}

// round 16
// speedup vs baseline: 1.5797x; 1.0102x over previous
#include <cuda_runtime.h>
#include <cuda_fp16.h>
#include <math.h>

// Problem constants (fixed by setup_inputs): B=1, L=8192, H=16, D=64
#define H 16
#define L 8192
#define D 64
#define HD (H*D)      // 1024
#define BLKQ 64
#define BLKK 32
#define M 128         // L/BLKQ
#define N 256         // L/BLKK
#define T 25          // int(0.1 * N)
#define SCALE 0.125f
#define LOG2E 1.4426950408889634f
#define SC2 (SCALE*LOG2E)
#define INV_L (1.0f/8192.0f)
#define SKH 72        // smem row stride in halves (144B, 16B-multiple)
#define SVH 72
#define ONES16 0x3C003C00u   // half2(1.0, 1.0)

// Scratch (device globals; no allocation allowed)
__device__ float g_km[H*D];            // SUM of k over L
__device__ float g_pq[H*M*D];
__device__ float g_pkT[H*D*N];         // transposed raw pooled k: [h][d][n]
__device__ int   g_lut[H*M*T];
__device__ __half g_kh[H*L*D];         // centered k, fp16, [h][l][d]
__device__ __half g_vh[H*L*D];         // v, fp16, [h][l][d]
__device__ __half g_kfm[H*L*D];        // softmax feature map of k, fp16, [h][l][d]
__device__ float g_kvsum[H*D*D];
__device__ __half g_kvwh[H*D*D];       // (kvsum @ W^T)^T per head, fp16, [h][e][d]
__device__ float g_ksum[H*D];

// ---------------------------------------------------------------------------
// helpers
// ---------------------------------------------------------------------------
__device__ __forceinline__ float ex2(float x) {
    float r; asm("ex2.approx.f32 %0, %1;" : "=f"(r) : "f"(x)); return r;
}
__device__ __forceinline__ unsigned ex2h2(unsigned x) {
    unsigned r; asm("ex2.approx.f16x2 %0, %1;" : "=r"(r) : "r"(x)); return r;
}
__device__ __forceinline__ unsigned pk2(float lo, float hi) {
    __half2 h = __floats2half2_rn(lo, hi);
    return *(unsigned*)&h;
}
__device__ __forceinline__ void mma16(float* d, const unsigned* a, unsigned b0, unsigned b1) {
    asm volatile("mma.sync.aligned.m16n8k16.row.col.f32.f16.f16.f32 "
        "{%0,%1,%2,%3}, {%4,%5,%6,%7}, {%8,%9}, {%0,%1,%2,%3};"
        : "+f"(d[0]), "+f"(d[1]), "+f"(d[2]), "+f"(d[3])
        : "r"(a[0]), "r"(a[1]), "r"(a[2]), "r"(a[3]), "r"(b0), "r"(b1));
}
__device__ __forceinline__ void cpa16(unsigned sdst, const void* gsrc) {
    asm volatile("cp.async.cg.shared.global [%0], [%1], 16;" :: "r"(sdst), "l"(gsrc));
}
__device__ __forceinline__ void ldsm4(unsigned &r0, unsigned &r1, unsigned &r2,
                                      unsigned &r3, unsigned a) {
    asm volatile("ldmatrix.sync.aligned.m8n8.x4.shared.b16 {%0,%1,%2,%3}, [%4];"
        : "=r"(r0), "=r"(r1), "=r"(r2), "=r"(r3) : "r"(a));
}
__device__ __forceinline__ void ldsm4t(unsigned &r0, unsigned &r1, unsigned &r2,
                                       unsigned &r3, unsigned a) {
    asm volatile("ldmatrix.sync.aligned.m8n8.x4.trans.shared.b16 {%0,%1,%2,%3}, [%4];"
        : "=r"(r0), "=r"(r1), "=r"(r2), "=r"(r3) : "r"(a));
}

// ---------------------------------------------------------------------------
// K0: zero accumulators
// ---------------------------------------------------------------------------
__global__ void k_zero() {
    int t = blockIdx.x*256 + threadIdx.x;
    if (t < H*D*D) g_kvsum[t] = 0.f;
    if (t < H*D) { g_ksum[t] = 0.f; g_km[t] = 0.f; }
}

// ---------------------------------------------------------------------------
// K2: merged block pooling (q and k) + k-sum accumulation
// ---------------------------------------------------------------------------
__global__ void k_pool(const float* __restrict__ q, const float* __restrict__ k) {
    int h = blockIdx.y, d = threadIdx.x, bx = blockIdx.x;
    if (bx < M) {
        float acc = 0.f;
        #pragma unroll 4
        for (int r = 0; r < BLKQ; r++) acc += q[(bx*BLKQ + r)*HD + h*D + d];
        g_pq[(h*M + bx)*D + d] = acc / (float)BLKQ;
    } else {
        int n = bx - M;
        float acc = 0.f;
        #pragma unroll 4
        for (int r = 0; r < BLKK; r++) acc += k[(n*BLKK + r)*HD + h*D + d];
        g_pkT[(h*D + d)*N + n] = acc / (float)BLKK;
        atomicAdd(&g_km[h*D + d], acc);
    }
}

// ---------------------------------------------------------------------------
// K3: routing + top-25. grid (M, H), 512 threads; split rank loop.
// ---------------------------------------------------------------------------
__global__ __launch_bounds__(512) void k_topk() {
    int m = blockIdx.x, h = blockIdx.y, t = threadIdx.x;
    int n = t & 255, half = t >> 8;
    __shared__ float pq[64];
    __shared__ unsigned long long keys[N];
    __shared__ int r2[2][N];
    __shared__ int warpoff[8];
    if (t < 64) pq[t] = g_pq[(h*M + m)*D + t];
    __syncthreads();
    if (half == 0) {
        float s = 0.f;
        #pragma unroll 8
        for (int d = 0; d < 64; d++)
            s += pq[d] * g_pkT[(h*D + d)*N + n];
        unsigned sb = __float_as_uint(s);
        sb ^= (sb >> 31) ? 0xFFFFFFFFu : 0x80000000u;
        keys[n] = ((unsigned long long)sb << 32) | (unsigned)(N - 1 - n);
    }
    __syncthreads();
    unsigned long long mykey = keys[n];
    int rank = 0;
    int j0 = half * 128;
    #pragma unroll 8
    for (int j = j0; j < j0 + 128; j += 2) {
        ulonglong2 kk = *(ulonglong2*)&keys[j];
        rank += (kk.x > mykey) + (kk.y > mykey);
    }
    r2[half][n] = rank;
    __syncthreads();
    int w = t >> 5, lane = t & 31;
    bool sel = false;
    if (half == 0) sel = (r2[0][n] + r2[1][n]) < T;
    unsigned bal = __ballot_sync(0xffffffffu, sel);
    if (half == 0 && lane == 0) warpoff[w] = __popc(bal);
    __syncthreads();
    if (sel) {
        int pos = __popc(bal & ((1u << lane) - 1u));
        for (int i = 0; i < w; i++) pos += warpoff[i];
        g_lut[(h*M + m)*T + pos] = n;
    }
}

// ---------------------------------------------------------------------------
// K3b: convert pass — row-major fp16 outputs, no transposes, all coalesced.
// grid (256, H), 256 threads; 32 l per block, warp handles 4 rows.
// ---------------------------------------------------------------------------
__global__ __launch_bounds__(256) void k_conv(const float* __restrict__ k,
                                              const float* __restrict__ v) {
    int c = blockIdx.x, h = blockIdx.y;
    int t = threadIdx.x, w = t >> 5, lane = t & 31;
    int lc = c * 32;
    __shared__ float skm[64];
    __shared__ float sks[64];
    if (t < 64) { skm[t] = g_km[h*D + t] * INV_L; sks[t] = 0.f; }
    __syncthreads();
    float km0 = skm[2*lane], km1 = skm[2*lane + 1];
    float ka0 = 0.f, ka1 = 0.f;
    #pragma unroll
    for (int rr = 0; rr < 4; rr++) {
        int l = lc + w*4 + rr;
        float2 x = *(const float2*)&k[l*HD + h*D + 2*lane];
        float e0 = ex2(x.x * LOG2E), e1 = ex2(x.y * LOG2E);
        float sm = e0 + e1;
        #pragma unroll
        for (int off = 16; off > 0; off >>= 1)
            sm += __shfl_xor_sync(0xffffffffu, sm, off);
        float inv = 1.f / sm;
        float f0 = e0*inv, f1 = e1*inv;
        *(__half2*)&g_kfm[(h*L + l)*D + 2*lane] = __floats2half2_rn(f0, f1);
        *(__half2*)&g_kh [(h*L + l)*D + 2*lane] = __floats2half2_rn(x.x - km0, x.y - km1);
        ka0 += f0; ka1 += f1;
    }
    atomicAdd(&sks[2*lane],     ka0);
    atomicAdd(&sks[2*lane + 1], ka1);
    #pragma unroll
    for (int j = 0; j < 4; j++) {
        int i = t + j*256;
        int row = i >> 5, d2 = (i & 31)*2;
        int l = lc + row;
        float2 vv = *(const float2*)&v[l*HD + h*D + d2];
        *(__half2*)&g_vh[(h*L + l)*D + d2] = __floats2half2_rn(vv.x, vv.y);
    }
    __syncthreads();
    if (t < 64) atomicAdd(&g_ksum[h*D + t], sks[t]);
}

// ---------------------------------------------------------------------------
// K5: kvsum[d][e] = sum_l kfm[l][d]*v[l][e] via tensor cores with trans
// ldmatrix (A = kfm^T, B = v, both row-major [l][.]). grid (16, H), 128 thr.
// ---------------------------------------------------------------------------
__global__ __launch_bounds__(128) void k_kvsum() {
    __shared__ __half sa[2][64*SKH];
    __shared__ __half sb[2][64*SVH];
    int c = blockIdx.x, h = blockIdx.y;
    int t = threadIdx.x, w = t >> 5, lane = t & 31;
    int g = lane >> 2, t4 = lane & 3;
    int lbase = c * 512;
    int m0 = w*16;

    auto issue = [&](int buf, int it) {
        #pragma unroll
        for (int j = 0; j < 4; j++) {
            int ch = t + j*128;
            int row = ch >> 3, c8 = (ch & 7)*8;
            cpa16((unsigned)__cvta_generic_to_shared(&sa[buf][row*SKH + c8]),
                  g_kfm + (h*L + lbase + it*64 + row)*D + c8);
            cpa16((unsigned)__cvta_generic_to_shared(&sb[buf][row*SVH + c8]),
                  g_vh  + (h*L + lbase + it*64 + row)*D + c8);
        }
        asm volatile("cp.async.commit_group;" ::: "memory");
    };

    issue(0, 0);
    issue(1, 1);

    unsigned aoff = ((((lane>>4)&1)*8 + (lane&7))*SKH)*2 + (((lane>>3)&1)*8 + m0)*2;
    unsigned boff = ((((lane>>3)&1)*8 + (lane&7))*SVH)*2 + ((lane>>4)*8)*2;

    float o[8][4];
    #pragma unroll
    for (int i = 0; i < 8; i++) { o[i][0]=0.f; o[i][1]=0.f; o[i][2]=0.f; o[i][3]=0.f; }

    for (int it = 0; it < 8; it++) {
        if (it + 1 < 8) asm volatile("cp.async.wait_group 1;" ::: "memory");
        else            asm volatile("cp.async.wait_group 0;" ::: "memory");
        __syncthreads();
        unsigned saB = (unsigned)__cvta_generic_to_shared(sa[it & 1]);
        unsigned sbB = (unsigned)__cvta_generic_to_shared(sb[it & 1]);
        #pragma unroll
        for (int ks = 0; ks < 4; ks++) {
            unsigned aa[4];
            ldsm4t(aa[0], aa[1], aa[2], aa[3], saB + aoff + ks*16*(SKH*2));
            #pragma unroll
            for (int j = 0; j < 4; j++) {
                unsigned r0, r1, r2, r3;
                ldsm4t(r0, r1, r2, r3, sbB + boff + ks*16*(SVH*2) + j*32);
                mma16(o[2*j],     aa, r0, r1);
                mma16(o[2*j + 1], aa, r2, r3);
            }
        }
        __syncthreads();
        if (it + 2 < 8) issue(it & 1, it + 2);
    }

    int d0 = w*16 + g;
    #pragma unroll
    for (int nt = 0; nt < 8; nt++) {
        int e = nt*8 + 2*t4;
        atomicAdd(&g_kvsum[h*4096 + d0*64 + e],       o[nt][0]);
        atomicAdd(&g_kvsum[h*4096 + d0*64 + e + 1],   o[nt][1]);
        atomicAdd(&g_kvsum[h*4096 + (d0+8)*64 + e],   o[nt][2]);
        atomicAdd(&g_kvsum[h*4096 + (d0+8)*64 + e+1], o[nt][3]);
    }
}

// ---------------------------------------------------------------------------
// K5b: kvwh[h][e][d] = fp16( sum_f kvsum[h][d][f] * W[e][f] )  (transposed)
// ---------------------------------------------------------------------------
__global__ void k_kvw(const float* __restrict__ W) {
    int h = blockIdx.x, t = threadIdx.x;    // 256 threads
    __shared__ float kvs[4096];
    __shared__ float WT[64*68];             // [f][e]
    __shared__ __half ob[64*SKH];           // [e][d]
    for (int i = t; i < 4096; i += 256) {
        kvs[i] = g_kvsum[h*4096 + i];
        int e = i >> 6, f = i & 63;
        WT[f*68 + e] = W[i];
    }
    __syncthreads();
    int d = t >> 2, eg = (t & 3) * 16;
    float4 a[4];
    #pragma unroll
    for (int j = 0; j < 4; j++) a[j] = make_float4(0.f, 0.f, 0.f, 0.f);
    #pragma unroll 4
    for (int f = 0; f < 64; f++) {
        float kv = kvs[d*64 + f];
        #pragma unroll
        for (int j = 0; j < 4; j++) {
            float4 wv = *(float4*)&WT[f*68 + eg + j*4];
            a[j].x += kv*wv.x; a[j].y += kv*wv.y; a[j].z += kv*wv.z; a[j].w += kv*wv.w;
        }
    }
    #pragma unroll
    for (int j = 0; j < 4; j++) {
        ob[(eg + j*4 + 0)*SKH + d] = __float2half_rn(a[j].x);
        ob[(eg + j*4 + 1)*SKH + d] = __float2half_rn(a[j].y);
        ob[(eg + j*4 + 2)*SKH + d] = __float2half_rn(a[j].z);
        ob[(eg + j*4 + 3)*SKH + d] = __float2half_rn(a[j].w);
    }
    __syncthreads();
    __half2* out2 = (__half2*)g_kvwh;
    for (int i = t; i < 2048; i += 256) {
        int e = i >> 5, d2 = (i & 31)*2;
        out2[(h*4096 + e*64 + d2) >> 1] =
            __halves2half2(ob[e*SKH + d2], ob[e*SKH + d2 + 1]);
    }
}

// ---------------------------------------------------------------------------
// K4: FUSED sparse attention + linear finalize. grid (M, H), 128 threads =
// 4 warps x 16 rows. fp16x2 ex2 (half MUFU); row sums via ones-B mma
// (numerator/denominator use IDENTICAL fp16 weights; no shuffles, no FADDs).
// Triple-buffered cp.async, one sync per stage. Epilogue overlays stage smem.
// ---------------------------------------------------------------------------
#define SKB (32*SKH*2)   // 4608
#define SVB (32*SVH*2)   // 4608
#define LOOPB (3*(SKB + SVB))  // 27648

__device__ __forceinline__ void issue_stage(__half* skbuf, __half* svbuf,
                                            int base, int h, int t) {
    #pragma unroll
    for (int j = 0; j < 2; j++) {
        int ch = t + j*128;              // 0..255
        int row = ch >> 3, c8 = (ch & 7)*8;
        cpa16((unsigned)__cvta_generic_to_shared(skbuf + row*SKH + c8),
              g_kh + (h*L + base + row)*D + c8);
        cpa16((unsigned)__cvta_generic_to_shared(svbuf + row*SVH + c8),
              g_vh + (h*L + base + row)*D + c8);
    }
    asm volatile("cp.async.commit_group;" ::: "memory");
}

__global__ __launch_bounds__(128, 4) void k_sparse(const float* __restrict__ q,
                                                   const float* __restrict__ bias,
                                                   float* __restrict__ out) {
    __shared__ __align__(16) char smraw[LOOPB];
    __shared__ float sksum[64], sbias[64], sinv[64];
    __shared__ int slut[32];
    __half* skbuf[3] = {(__half*)(smraw), (__half*)(smraw + SKB),
                        (__half*)(smraw + 2*SKB)};
    __half* svbuf[3] = {(__half*)(smraw + 3*SKB), (__half*)(smraw + 3*SKB + SVB),
                        (__half*)(smraw + 3*SKB + 2*SVB)};
    __half* skvw = (__half*)(smraw);            // epilogue overlay [e][d] 9216B
    __half* sqf  = (__half*)(smraw + 9216);     // epilogue overlay [l][d] 9216B

    int m = blockIdx.x, h = blockIdx.y;
    int t = threadIdx.x, w = t >> 5, lane = t & 31;
    int g = lane >> 2, t4 = lane & 3;

    const int* lut = &g_lut[(h*M + m)*T];
    issue_stage(skbuf[0], svbuf[0], __ldg(&lut[0])*BLKK, h, t);
    issue_stage(skbuf[1], svbuf[1], __ldg(&lut[1])*BLKK, h, t);
    if (t < T) slut[t] = lut[t];
    if (t < 64) { sksum[t] = g_ksum[h*D + t]; sbias[t] = bias[t]; }

    // q A-fragments directly from global (fp16)
    const float* qr0 = q + (m*64 + w*16 + g)*HD + h*D;
    const float* qr1 = qr0 + 8*HD;
    unsigned qa[4][4];
    #pragma unroll
    for (int ks = 0; ks < 4; ks++) {
        float2 a0 = *(const float2*)&qr0[ks*16 + 2*t4];
        float2 b0 = *(const float2*)&qr1[ks*16 + 2*t4];
        float2 a1 = *(const float2*)&qr0[ks*16 + 2*t4 + 8];
        float2 b1 = *(const float2*)&qr1[ks*16 + 2*t4 + 8];
        qa[ks][0] = pk2(a0.x, a0.y);
        qa[ks][1] = pk2(b0.x, b0.y);
        qa[ks][2] = pk2(a1.x, a1.y);
        qa[ks][3] = pk2(b1.x, b1.y);
    }

    unsigned lK = lane*(SKH*2);
    unsigned svoff = (((lane>>3)&1)*8 + (lane&7))*(SVH*2) + (lane>>4)*16;

    float rs[4] = {0.f, 0.f, 0.f, 0.f};   // ones-mma row sums (cols replicated)
    float o[8][4];
    #pragma unroll
    for (int i = 0; i < 8; i++) { o[i][0]=0.f; o[i][1]=0.f; o[i][2]=0.f; o[i][3]=0.f; }

    for (int tt = 0; tt < T; tt++) {
        if (tt + 1 < T) asm volatile("cp.async.wait_group 1;" ::: "memory");
        else            asm volatile("cp.async.wait_group 0;" ::: "memory");
        __syncthreads();
        if (tt + 2 < T)
            issue_stage(skbuf[(tt+2)%3], svbuf[(tt+2)%3], slut[tt+2]*BLKK, h, t);

        unsigned bk  = (unsigned)__cvta_generic_to_shared(skbuf[tt%3]) + lK;
        unsigned svB = (unsigned)__cvta_generic_to_shared(svbuf[tt%3]) + svoff;

        // ---- QK: ldmatrix.x4 B-frags, 4 k-steps x 4 n-tiles ----
        float s[4][4];
        #pragma unroll
        for (int nt = 0; nt < 4; nt++) { s[nt][0]=0.f; s[nt][1]=0.f; s[nt][2]=0.f; s[nt][3]=0.f; }
        #pragma unroll
        for (int ks = 0; ks < 4; ks++) {
            unsigned c0[4], c1[4];
            ldsm4(c0[0], c0[1], c0[2], c0[3], bk + ks*32);
            ldsm4(c1[0], c1[1], c1[2], c1[3], bk + ks*32 + 16);
            #pragma unroll
            for (int nt = 0; nt < 4; nt++)
                mma16(s[nt], qa[ks], c0[nt], c1[nt]);
        }
        // ---- p = exp2(s*SC2) in fp16x2; results ARE the PV A-fragments ----
        unsigned pa[2][4];
        #pragma unroll
        for (int nt = 0; nt < 4; nt++) {
            unsigned plo = ex2h2(pk2(s[nt][0]*SC2, s[nt][1]*SC2));
            unsigned phi = ex2h2(pk2(s[nt][2]*SC2, s[nt][3]*SC2));
            int k2 = nt >> 1, idx = (nt & 1)*2;
            pa[k2][idx]     = plo;
            pa[k2][idx + 1] = phi;
        }
        // ---- row sums of the SAME fp16 weights via ones-B mma ----
        mma16(rs, pa[0], ONES16, ONES16);
        mma16(rs, pa[1], ONES16, ONES16);
        // ---- PV: trans-ldmatrix V B-frags from row-major tile ----
        #pragma unroll
        for (int ks2 = 0; ks2 < 2; ks2++) {
            unsigned sb2 = svB + ks2*16*(SVH*2);
            #pragma unroll
            for (int j = 0; j < 4; j++) {
                unsigned r0, r1, r2, r3;
                ldsm4t(r0, r1, r2, r3, sb2 + j*32);
                mma16(o[2*j],   pa[ks2], r0, r1);
                mma16(o[2*j+1], pa[ks2], r2, r3);
            }
        }
    }

    // rs columns are replicated row sums: rs[0] = row g, rs[2] = row g+8
    float inv0 = 1.f / rs[0], inv1 = 1.f / rs[2];

    __syncthreads();   // stage buffers dead; overlay safe

    // load kvwh into overlay smem
    for (int i = t; i < 1024; i += 128) {
        int e = i >> 4, c4 = (i & 15)*4;
        *(uint2*)&skvw[e*SKH + c4] = *(const uint2*)&g_kvwh[(h*64 + e)*64 + c4];
    }
    // q feature map (no-max softmax) for own warp's 16 rows
    for (int rr = 0; rr < 16; rr++) {
        int row = w*16 + rr;
        int l = m*64 + row;
        float2 x = *(const float2*)&q[l*HD + h*D + 2*lane];
        float e0 = ex2(x.x * LOG2E), e1 = ex2(x.y * LOG2E);
        float sm = e0 + e1;
        #pragma unroll
        for (int off = 16; off > 0; off >>= 1)
            sm += __shfl_xor_sync(0xffffffffu, sm, off);
        float inv = 1.f / sm;
        float q0 = e0*inv, q1 = e1*inv;
        *(__half2*)&sqf[row*SKH + 2*lane] = __floats2half2_rn(q0, q1);
        float dp = q0*sksum[2*lane] + q1*sksum[2*lane + 1];
        #pragma unroll
        for (int off = 16; off > 0; off >>= 1)
            dp += __shfl_xor_sync(0xffffffffu, dp, off);
        if (lane == 0) sinv[row] = 1.f / (dp + 1e-6f);
    }
    __syncthreads();   // skvw + sqf visible to all warps

    float ol[8][4];
    #pragma unroll
    for (int i = 0; i < 8; i++) { ol[i][0]=0.f; ol[i][1]=0.f; ol[i][2]=0.f; ol[i][3]=0.f; }
    #pragma unroll
    for (int ks = 0; ks < 4; ks++) {
        unsigned aa[4];
        int cc = ks*16 + 2*t4;
        aa[0] = *(const unsigned*)&sqf[(w*16 + g    )*SKH + cc];
        aa[1] = *(const unsigned*)&sqf[(w*16 + g + 8)*SKH + cc];
        aa[2] = *(const unsigned*)&sqf[(w*16 + g    )*SKH + cc + 8];
        aa[3] = *(const unsigned*)&sqf[(w*16 + g + 8)*SKH + cc + 8];
        #pragma unroll
        for (int nt = 0; nt < 8; nt++) {
            unsigned b0 = *(const unsigned*)&skvw[(nt*8 + g)*SKH + cc];
            unsigned b1 = *(const unsigned*)&skvw[(nt*8 + g)*SKH + cc + 8];
            mma16(ol[nt], aa, b0, b1);
        }
    }

    // ---- combine + write out [l][h][d] ----
    int rg = w*16 + g;
    int l0 = m*64 + rg;
    float iv0 = sinv[rg], iv1 = sinv[rg + 8];
    #pragma unroll
    for (int nt = 0; nt < 8; nt++) {
        int col = nt*8 + 2*t4;
        *(float2*)&out[(l0    )*HD + h*D + col] =
            make_float2(o[nt][0]*inv0 + ol[nt][0]*iv0 + sbias[col],
                        o[nt][1]*inv0 + ol[nt][1]*iv0 + sbias[col+1]);
        *(float2*)&out[(l0 + 8)*HD + h*D + col] =
            make_float2(o[nt][2]*inv1 + ol[nt][2]*iv1 + sbias[col],
                        o[nt][3]*inv1 + ol[nt][3]*iv1 + sbias[col+1]);
    }
}

// ---------------------------------------------------------------------------
extern "C" void kernel_launch(void* const* d_in, const int* in_sizes, int n_in,
                              void* d_out, int out_size) {
    const float* q = (const float*)d_in[0];
    const float* k = (const float*)d_in[1];
    const float* v = (const float*)d_in[2];
    const float* W = (const float*)d_in[3];
    const float* b = (const float*)d_in[4];
    float* out = (float*)d_out;

    k_zero  <<<(H*D*D + 255)/256, 256>>>();
    k_pool  <<<dim3(M + N, H), 64>>>(q, k);
    k_topk  <<<dim3(M, H), 512>>>();
    k_conv  <<<dim3(256, H), 256>>>(k, v);
    k_kvsum <<<dim3(16, H), 128>>>();
    k_kvw   <<<H, 256>>>(W);
    k_sparse<<<dim3(M, H), 128>>>(q, b, out);
}